// round 5
// baseline (speedup 1.0000x reference)
#include <cuda_runtime.h>
#include <cuda_bf16.h>

#define N_VOX 400000
#define CCH   32
#define KK    27
#define SMEM_BYTES (KK * CCH * CCH * 4)   // 110592 B

// scratch for intermediate features h1 (51.2 MB, static device global — no alloc)
__device__ float g_h[(size_t)N_VOX * CCH];

// One warp per voxel (lane = output channel). W tile (27*32*32 f32) staged in SMEM.
// FINAL=false: out = relu(LN(conv(x)))
// FINAL=true : out = relu(LN(conv(x)) + resid)
template <bool FINAL>
__global__ void __launch_bounds__(1024, 1)
conv_ln_kernel(const float* __restrict__ feats,
               const float* __restrict__ resid,
               const int*   __restrict__ nbr,
               const float* __restrict__ W,
               const float* __restrict__ gamma,
               const float* __restrict__ beta,
               float* __restrict__ out)
{
    extern __shared__ float Ws[];
    for (int t = threadIdx.x; t < KK * CCH * CCH; t += blockDim.x)
        Ws[t] = W[t];
    __syncthreads();

    const int lane   = threadIdx.x & 31;
    const int warp   = (blockIdx.x * blockDim.x + threadIdx.x) >> 5;
    const int nwarps = (gridDim.x * blockDim.x) >> 5;

    const float gl = gamma[lane];
    const float bl = beta[lane];

    for (int i = warp; i < N_VOX; i += nwarps) {
        // lanes 0..26 each fetch one neighbor index for this voxel
        int my_idx = (lane < KK) ? nbr[lane * N_VOX + i] : -1;

        float acc = 0.0f;
        #pragma unroll 1
        for (int k = 0; k < KK; k++) {
            int idx = __shfl_sync(0xffffffffu, my_idx, k);
            if (idx >= 0) {                       // warp-uniform branch
                float g = feats[idx * CCH + lane];   // coalesced 128B gather
                const float* Wk = Ws + k * (CCH * CCH);
                #pragma unroll
                for (int cin = 0; cin < CCH; cin++) {
                    float gv = __shfl_sync(0xffffffffu, g, cin);
                    acc = fmaf(gv, Wk[cin * CCH + lane], acc);
                }
            }
        }

        // LayerNorm over the 32 channels (one warp)
        float s = acc;
        #pragma unroll
        for (int o = 16; o; o >>= 1) s += __shfl_xor_sync(0xffffffffu, s, o);
        float mu = s * (1.0f / 32.0f);
        float d  = acc - mu;
        float v  = d * d;
        #pragma unroll
        for (int o = 16; o; o >>= 1) v += __shfl_xor_sync(0xffffffffu, v, o);
        v *= (1.0f / 32.0f);

        float h = d * rsqrtf(v + 1e-6f) * gl + bl;
        if (FINAL) h += resid[i * CCH + lane];
        out[i * CCH + lane] = fmaxf(h, 0.0f);
    }
}

extern "C" void kernel_launch(void* const* d_in, const int* in_sizes, int n_in,
                              void* d_out, int out_size)
{
    const float* x   = (const float*)d_in[0];
    const int*   nbr = (const int*)  d_in[1];
    const float* W1  = (const float*)d_in[2];
    const float* g1  = (const float*)d_in[3];
    const float* b1  = (const float*)d_in[4];
    const float* W2  = (const float*)d_in[5];
    const float* g2  = (const float*)d_in[6];
    const float* b2  = (const float*)d_in[7];
    float* out = (float*)d_out;

    void* hptr = nullptr;
    cudaGetSymbolAddress(&hptr, g_h);
    float* h = (float*)hptr;

    cudaFuncSetAttribute(conv_ln_kernel<false>,
                         cudaFuncAttributeMaxDynamicSharedMemorySize, SMEM_BYTES);
    cudaFuncSetAttribute(conv_ln_kernel<true>,
                         cudaFuncAttributeMaxDynamicSharedMemorySize, SMEM_BYTES);

    const int threads = 1024;
    const int blocks  = 296;   // persistent-ish grid-stride; ~43 voxels per warp

    conv_ln_kernel<false><<<blocks, threads, SMEM_BYTES>>>(x, nullptr, nbr, W1, g1, b1, h);
    conv_ln_kernel<true ><<<blocks, threads, SMEM_BYTES>>>(h, x,       nbr, W2, g2, b2, out);
}

// round 11
// speedup vs baseline: 1.6382x; 1.6382x over previous
#include <cuda_runtime.h>
#include <cuda_bf16.h>
#include <cstdint>

#define N_VOX  400000
#define MTILE  384
#define NTILES 1042          // ceil(400000/384)
#define KK     27

// SMEM: [0) gamma 128B | [128) beta 128B | [1024) W 27*4096B | [111616) A 384*128B
#define SM_G    0
#define SM_BETA 128
#define SM_W    1024
#define SM_A    111616
#define SMEM_TOTAL (SM_A + MTILE * 128)   // 160768

__device__ float g_h[(size_t)N_VOX * 32];

static __device__ __forceinline__ uint32_t smem_u32(const void* p) {
    uint32_t a;
    asm("{ .reg .u64 t; cvta.to.shared.u64 t, %1; cvt.u32.u64 %0, t; }" : "=r"(a) : "l"(p));
    return a;
}
static __device__ __forceinline__ uint32_t pk2(float a, float b) {
    __nv_bfloat162 h = __floats2bfloat162_rn(a, b);
    return *reinterpret_cast<uint32_t*>(&h);
}
static __device__ __forceinline__ float bfh(float x) {
    return __bfloat162float(__float2bfloat16_rn(x));
}
static __device__ __forceinline__ void ldsm4(uint32_t* r, uint32_t addr) {
    asm volatile("ldmatrix.sync.aligned.m8n8.x4.shared.b16 {%0,%1,%2,%3}, [%4];"
                 : "=r"(r[0]), "=r"(r[1]), "=r"(r[2]), "=r"(r[3]) : "r"(addr));
}
static __device__ __forceinline__ void mma16816(float* d, const uint32_t* a,
                                                uint32_t b0, uint32_t b1) {
    asm volatile("mma.sync.aligned.m16n8k16.row.col.f32.bf16.bf16.f32 "
                 "{%0,%1,%2,%3},{%4,%5,%6,%7},{%8,%9},{%0,%1,%2,%3};"
                 : "+f"(d[0]), "+f"(d[1]), "+f"(d[2]), "+f"(d[3])
                 : "r"(a[0]), "r"(a[1]), "r"(a[2]), "r"(a[3]), "r"(b0), "r"(b1));
}

template <bool FINAL>
__global__ void __launch_bounds__(MTILE, 1)
conv_hmma(const float* __restrict__ feats, const float* __restrict__ resid,
          const int* __restrict__ nbr, const float* __restrict__ Wg,
          const float* __restrict__ gamma, const float* __restrict__ beta,
          float* __restrict__ out)
{
    extern __shared__ char smem[];
    const uint32_t sb  = smem_u32(smem);
    const int tid = threadIdx.x, wid = tid >> 5, lane = tid & 31;

    if (tid < 32) {
        ((float*)(smem + SM_G))[tid]    = gamma[tid];
        ((float*)(smem + SM_BETA))[tid] = beta[tid];
    }

    // ---- W prep: [k][cin][cout] -> rows of cout: [Wh 64B | Wl 64B], chunk-swizzled ----
    {
        float* stage = (float*)(smem + SM_A);
        for (int k = 0; k < KK; k++) {
            stage[tid]       = Wg[k * 1024 + tid];
            stage[tid + 384] = Wg[k * 1024 + tid + 384];
            if (tid < 256) stage[tid + 768] = Wg[k * 1024 + tid + 768];
            __syncthreads();
            if (tid < 256) {
                const int cout = tid & 31, g4 = tid >> 5;   // g4: group of 4 cins
                float w[4], wh[4];
                #pragma unroll
                for (int j = 0; j < 4; j++) {
                    w[j]  = stage[(g4 * 4 + j) * 32 + cout];
                    wh[j] = bfh(w[j]);
                }
                uint2 hi = make_uint2(pk2(w[0], w[1]), pk2(w[2], w[3]));
                uint2 lo = make_uint2(pk2(w[0]-wh[0], w[1]-wh[1]), pk2(w[2]-wh[2], w[3]-wh[3]));
                char* wk = smem + SM_W + k * 4096 + cout * 128;
                const int s = cout & 7, ch = g4 >> 1, half8 = (g4 & 1) * 8;
                *(uint2*)(wk + ((ch ^ s) << 4) + half8)       = hi;
                *(uint2*)(wk + (((4 + ch) ^ s) << 4) + half8) = lo;
            }
            __syncthreads();
        }
    }

    const uint32_t a_base = sb + SM_A;
    // per-lane constant LDSM addressing components
    const int b_nrow = (lane & 7) + ((lane >> 4) << 3);      // B: n-row within 16-group
    const int b_chof = (lane >> 3) & 1;                      // B: k-octet select
    const int a_rofs = (lane & 7) + (lane & 8);              // A: row within 16-group
    const int a_chof = (lane >> 4);                          // A: k-octet select

    for (int tile = blockIdx.x; tile < NTILES; tile += gridDim.x) {
        const int base = tile * MTILE;
        const int gidx = base + tid;
        const bool inb = gidx < N_VOX;

        float acc[2][4][4];
        #pragma unroll
        for (int mi = 0; mi < 2; mi++)
            #pragma unroll
            for (int nb = 0; nb < 4; nb++)
                #pragma unroll
                for (int q = 0; q < 4; q++) acc[mi][nb][q] = 0.f;

        int i0 = inb ? nbr[gidx] : -1;
        int i1 = inb ? nbr[N_VOX + gidx] : -1;
        float4 f[8];
        {
            const float4* p = (const float4*)(feats + (size_t)(i0 >= 0 ? i0 : 0) * 32);
            #pragma unroll
            for (int j = 0; j < 8; j++) f[j] = (i0 >= 0) ? p[j] : make_float4(0.f,0.f,0.f,0.f);
        }

        #pragma unroll 1
        for (int k = 0; k < KK; k++) {
            const int i2 = (k + 2 < KK && inb) ? nbr[(size_t)(k + 2) * N_VOX + gidx] : -1;
            const uint32_t mask = __ballot_sync(0xffffffffu, i0 >= 0);
            const uint32_t hm   = (lane < 16) ? (mask & 0xffffu) : (mask >> 16);

            __syncwarp();          // epilogue/LDSM of previous use done before overwrite
            if (hm) {              // my 16-row half will be consumed -> must store (zeros ok)
                uint32_t hi[16], lo[16];
                #pragma unroll
                for (int j = 0; j < 8; j++) {
                    float4 q = f[j];
                    float hx = bfh(q.x), hy = bfh(q.y), hz = bfh(q.z), hw = bfh(q.w);
                    hi[2*j]   = pk2(q.x, q.y);       hi[2*j+1] = pk2(q.z, q.w);
                    lo[2*j]   = pk2(q.x-hx, q.y-hy); lo[2*j+1] = pk2(q.z-hz, q.w-hw);
                }
                char* arow = smem + SM_A + tid * 128;
                const int s = tid & 7;
                #pragma unroll
                for (int c = 0; c < 4; c++) {
                    *(uint4*)(arow + ((c ^ s) << 4))       = make_uint4(hi[4*c], hi[4*c+1], hi[4*c+2], hi[4*c+3]);
                    *(uint4*)(arow + (((4+c) ^ s) << 4))   = make_uint4(lo[4*c], lo[4*c+1], lo[4*c+2], lo[4*c+3]);
                }
            }
            __syncwarp();

            // prefetch next tap's features (overwrites f; hidden under LDSM/MMA below)
            {
                const bool an = (i1 >= 0);
                const float4* p = (const float4*)(feats + (size_t)(an ? i1 : 0) * 32);
                #pragma unroll
                for (int j = 0; j < 8; j++) f[j] = an ? p[j] : make_float4(0.f,0.f,0.f,0.f);
            }

            if (mask) {
                // B fragments for this tap: hi + lo, 4 x4-ldmatrix each
                uint32_t bh[4][4], bl[4][4];
                const uint32_t wbase = sb + SM_W + k * 4096;
                #pragma unroll
                for (int kb = 0; kb < 2; kb++)
                    #pragma unroll
                    for (int np = 0; np < 2; np++) {
                        const int n0 = np * 16 + b_nrow;
                        const int s  = n0 & 7;
                        const uint32_t rb = wbase + n0 * 128;
                        ldsm4(bh[kb*2+np], rb + (((2*kb + b_chof) ^ s) << 4));
                        ldsm4(bl[kb*2+np], rb + (((4 + 2*kb + b_chof) ^ s) << 4));
                    }
                const uint32_t mlo = mask & 0xffffu, mhi = mask >> 16;
                #pragma unroll
                for (int mi = 0; mi < 2; mi++) {
                    if (mi ? mhi : mlo) {
                        uint32_t ah[8], al[8];
                        const int arow = (wid << 5) + mi * 16 + a_rofs;
                        const int s    = arow & 7;
                        const uint32_t ra = a_base + arow * 128;
                        #pragma unroll
                        for (int kb = 0; kb < 2; kb++) {
                            ldsm4(ah + kb*4, ra + (((2*kb + a_chof) ^ s) << 4));
                            ldsm4(al + kb*4, ra + (((4 + 2*kb + a_chof) ^ s) << 4));
                        }
                        #pragma unroll
                        for (int nb = 0; nb < 4; nb++) {
                            const int np = nb >> 1, sel = (nb & 1) * 2;
                            #pragma unroll
                            for (int kb = 0; kb < 2; kb++) {
                                mma16816(acc[mi][nb], ah + kb*4, bh[kb*2+np][sel], bh[kb*2+np][sel+1]);
                                mma16816(acc[mi][nb], al + kb*4, bh[kb*2+np][sel], bh[kb*2+np][sel+1]);
                                mma16816(acc[mi][nb], ah + kb*4, bl[kb*2+np][sel], bl[kb*2+np][sel+1]);
                            }
                        }
                    }
                }
            }
            i0 = i1; i1 = i2;
        }

        // ---- epilogue: acc frags -> swizzled SMEM -> per-thread row LN ----
        __syncwarp();
        {
            const int r0 = (wid << 5) + (lane >> 2);
            const int cb = (lane & 3) * 8;                  // byte offset of col pair
            #pragma unroll
            for (int mi = 0; mi < 2; mi++) {
                const int row = r0 + mi * 16;
                const int s = row & 7;                      // (row+8)&7 == row&7
                char* rp  = smem + SM_A + row * 128;
                char* rp8 = smem + SM_A + (row + 8) * 128;
                #pragma unroll
                for (int nb = 0; nb < 4; nb++) {
                    const int byte0 = nb * 32 + cb;
                    const int ch = byte0 >> 4, off = byte0 & 15;
                    *(float2*)(rp  + ((ch ^ s) << 4) + off) = make_float2(acc[mi][nb][0], acc[mi][nb][1]);
                    *(float2*)(rp8 + ((ch ^ s) << 4) + off) = make_float2(acc[mi][nb][2], acc[mi][nb][3]);
                }
            }
        }
        __syncwarp();
        if (inb) {
            float v[32];
            const int s = tid & 7;
            const char* rp = smem + SM_A + tid * 128;
            #pragma unroll
            for (int c = 0; c < 8; c++) {
                float4 t4 = *(const float4*)(rp + ((c ^ s) << 4));
                v[4*c] = t4.x; v[4*c+1] = t4.y; v[4*c+2] = t4.z; v[4*c+3] = t4.w;
            }
            float sum = 0.f;
            #pragma unroll
            for (int c = 0; c < 32; c++) sum += v[c];
            const float mu = sum * (1.0f / 32.0f);
            float var = 0.f;
            #pragma unroll
            for (int c = 0; c < 32; c++) { float d = v[c] - mu; var += d * d; }
            const float rs = rsqrtf(var * (1.0f / 32.0f) + 1e-6f);
            const float* gs = (const float*)(smem + SM_G);
            const float* bs = (const float*)(smem + SM_BETA);
            float4* op = (float4*)(out + (size_t)gidx * 32);
            const float4* rpg = FINAL ? (const float4*)(resid + (size_t)gidx * 32) : nullptr;
            #pragma unroll
            for (int q = 0; q < 8; q++) {
                float4 o;
                o.x = (v[4*q+0] - mu) * rs * gs[4*q+0] + bs[4*q+0];
                o.y = (v[4*q+1] - mu) * rs * gs[4*q+1] + bs[4*q+1];
                o.z = (v[4*q+2] - mu) * rs * gs[4*q+2] + bs[4*q+2];
                o.w = (v[4*q+3] - mu) * rs * gs[4*q+3] + bs[4*q+3];
                if (FINAL) {
                    float4 rr = rpg[q];
                    o.x += rr.x; o.y += rr.y; o.z += rr.z; o.w += rr.w;
                }
                o.x = fmaxf(o.x, 0.f); o.y = fmaxf(o.y, 0.f);
                o.z = fmaxf(o.z, 0.f); o.w = fmaxf(o.w, 0.f);
                op[q] = o;
            }
        }
        // next-iteration pack is guarded by __syncwarp at loop top
    }
}

extern "C" void kernel_launch(void* const* d_in, const int* in_sizes, int n_in,
                              void* d_out, int out_size)
{
    const float* x   = (const float*)d_in[0];
    const int*   nbr = (const int*)  d_in[1];
    const float* W1  = (const float*)d_in[2];
    const float* g1  = (const float*)d_in[3];
    const float* b1  = (const float*)d_in[4];
    const float* W2  = (const float*)d_in[5];
    const float* g2  = (const float*)d_in[6];
    const float* b2  = (const float*)d_in[7];
    float* out = (float*)d_out;

    void* hptr = nullptr;
    cudaGetSymbolAddress(&hptr, g_h);
    float* h = (float*)hptr;

    cudaFuncSetAttribute(conv_hmma<false>,
                         cudaFuncAttributeMaxDynamicSharedMemorySize, SMEM_TOTAL);
    cudaFuncSetAttribute(conv_hmma<true>,
                         cudaFuncAttributeMaxDynamicSharedMemorySize, SMEM_TOTAL);

    conv_hmma<false><<<148, MTILE, SMEM_TOTAL>>>(x, nullptr, nbr, W1, g1, b1, h);
    conv_hmma<true ><<<148, MTILE, SMEM_TOTAL>>>(h, x,       nbr, W2, g2, b2, out);
}